// round 15
// baseline (speedup 1.0000x reference)
#include <cuda_runtime.h>
#include <string.h>

#define NN 512
#define H  64
#define ED 6
#define NL 4
#define EE (NN*NN)
#define LN_EPS 1e-5f

// Scratch (device globals: no allocations allowed)
__device__ float g_h  [NN*H];
__device__ float g_Hd [NN*H];         // dst-side attention proj (+att_b1), row-major
__device__ float g_HsT[2][H*NN];      // src-side attention proj, DIM-MAJOR [j][s], double buffered
__device__ float g_Av [2][NN*H];      // src-side value proj (+val_b1), row-major, double buffered
__device__ float g_eaT[ED*EE];        // edge_attr transposed: eaT[k][d][s]
__device__ float g_pm  [2*NN];        // per (2d+half) softmax partial max
__device__ float g_ps  [2*NN];        // per (2d+half) softmax partial sum
__device__ float g_pacc[2*NN*H];      // per (2d+half) weighted value partial

__device__ __forceinline__ float warp_sum(float v) {
#pragma unroll
    for (int o = 16; o; o >>= 1) v += __shfl_xor_sync(0xffffffffu, v, o);
    return v;
}
__device__ __forceinline__ float warp_max(float v) {
#pragma unroll
    for (int o = 16; o; o >>= 1) v = fmaxf(v, __shfl_xor_sync(0xffffffffu, v, o));
    return v;
}

// Packed fp32x2 ops (sm_103a): 2 fp32 FMAs per instruction
__device__ __forceinline__ float2 ffma2(float2 a, float2 b, float2 c) {
    unsigned long long ua, ub, uc, ur;
    memcpy(&ua, &a, 8); memcpy(&ub, &b, 8); memcpy(&uc, &c, 8);
    asm("fma.rn.f32x2 %0, %1, %2, %3;" : "=l"(ur) : "l"(ua), "l"(ub), "l"(uc));
    float2 r; memcpy(&r, &ur, 8); return r;
}
__device__ __forceinline__ float2 fadd2(float2 a, float2 b) {
    unsigned long long ua, ub, ur;
    memcpy(&ua, &a, 8); memcpy(&ub, &b, 8);
    asm("add.rn.f32x2 %0, %1, %2;" : "=l"(ur) : "l"(ua), "l"(ub));
    float2 r; memcpy(&r, &ur, 8); return r;
}
__device__ __forceinline__ float2 fmul2(float2 a, float2 b) {
    unsigned long long ua, ub, ur;
    memcpy(&ua, &a, 8); memcpy(&ub, &b, 8);
    asm("mul.rn.f32x2 %0, %1, %2;" : "=l"(ur) : "l"(ua), "l"(ub));
    float2 r; memcpy(&r, &ur, 8); return r;
}

// Per-node tables (encoder path): Hd, HsT (dim-major), Av
__device__ __forceinline__ void compute_tables(
    int d, int t, int wb, const float* h_sh,
    const float* __restrict__ attW1, const float* __restrict__ attB1,
    const float* __restrict__ valW1, const float* __restrict__ valB1)
{
    float ad = attB1[t], as = 0.f, av = valB1[t];
#pragma unroll 8
    for (int k = 0; k < H; k++) {
        float hk = h_sh[k];
        ad += hk * attW1[k * H + t];
        as += hk * attW1[(H + k) * H + t];
        av += hk * valW1[k * H + t];
    }
    g_Hd[d * H + t]       = ad;
    g_HsT[wb][t * NN + d] = as;
    g_Av[wb][d * H + t]   = av;
}

// Transpose edge_attr: ea[s][d][k] -> eaT[k][d][s]. grid (16,16), block 256.
__global__ void __launch_bounds__(256) ea_transpose_kernel(const float* __restrict__ ea)
{
    __shared__ float t_sh[ED][32][33];
    const int t = threadIdx.x, w = t >> 5, lane = t & 31;
    const int bs = blockIdx.x * 32, bd = blockIdx.y * 32;

#pragma unroll
    for (int rr = 0; rr < 4; rr++) {
        int s_loc = w + rr * 8;
        const float* base = ea + ((size_t)(bs + s_loc) * NN + bd) * ED + lane * ED;
        float2 v0 = *(const float2*)(base);
        float2 v1 = *(const float2*)(base + 2);
        float2 v2 = *(const float2*)(base + 4);
        t_sh[0][lane][s_loc] = v0.x; t_sh[1][lane][s_loc] = v0.y;
        t_sh[2][lane][s_loc] = v1.x; t_sh[3][lane][s_loc] = v1.y;
        t_sh[4][lane][s_loc] = v2.x; t_sh[5][lane][s_loc] = v2.y;
    }
    __syncthreads();
#pragma unroll
    for (int idx = t; idx < ED * 32 * 32; idx += 256) {
        int k = idx >> 10, r = idx & 1023, dl = r >> 5, sl = r & 31;
        g_eaT[(size_t)k * EE + (size_t)(bd + dl) * NN + bs + sl] = t_sh[k][dl][sl];
    }
}

// Encoder: h = relu(x@W1+b1)@W2+b2, then layer-0 tables (buffer 0). grid=512, block=64
__global__ void __launch_bounds__(H) enc_kernel(
    const float* __restrict__ x,
    const float* __restrict__ ew1, const float* __restrict__ eb1,
    const float* __restrict__ ew2, const float* __restrict__ eb2,
    const float* __restrict__ attW1, const float* __restrict__ attB1,
    const float* __restrict__ valW1, const float* __restrict__ valB1)
{
    int d = blockIdx.x, t = threadIdx.x;
    __shared__ float xs[ED], hid[H], hsn[H];
    if (t < ED) xs[t] = x[d * ED + t];
    __syncthreads();
    float a = eb1[t];
#pragma unroll
    for (int k = 0; k < ED; k++) a += xs[k] * ew1[k * H + t];
    hid[t] = fmaxf(a, 0.f);
    __syncthreads();
    float hv = eb2[t];
#pragma unroll 8
    for (int k = 0; k < H; k++) hv += hid[k] * ew2[k * H + t];
    g_h[d * H + t] = hv;
    hsn[t] = hv;
    __syncthreads();
    compute_tables(d, t, 0, hsn, attW1, attB1, valW1, valB1);
}

// Edge kernel (proven R8 structure): grid 1024 = 2 blocks per dst (half=bid&1,
// 256 srcs each), 128 threads = 4 warps; warp w owns local srcs [w*64,+64);
// lane owns the pair (2*lane, 2*lane+1). Pre-dup f32x2 smem operands, per-warp
// register softmax, block combine; partial (m,s,acc[64]) per (2d+half) to global.
__global__ void __launch_bounds__(128, 7) edge_kernel(
    const float* __restrict__ attW1e,   // [6,64] edge rows of att_w1[l]
    const float* __restrict__ attW2,    // [64]
    const float* __restrict__ valW1e,   // [6,64] edge rows of val_w1[l]
    int rb)
{
    const int bid = blockIdx.x;
    const int d = bid >> 1, half = bid & 1;
    const int t = threadIdx.x, w = t >> 5, lane = t & 31;

    __shared__ __align__(16) float4 wa4[H * 4];
    __shared__ __align__(16) float4 ea2[256 * 3];
    __shared__ __align__(16) float2 wexp2[256];
    __shared__ float pm[4], ps[4], pacc[4 * H];

    if (t < H) {
        int j = t;
        float w0 = attW1e[0 * H + j], w1 = attW1e[1 * H + j];
        float w2 = attW1e[2 * H + j], w3 = attW1e[3 * H + j];
        float w4 = attW1e[4 * H + j], w5 = attW1e[5 * H + j];
        float wo = attW2[j];
        float hd = g_Hd[d * H + j];
        wa4[j * 4 + 0] = make_float4(w0, w0, w1, w1);
        wa4[j * 4 + 1] = make_float4(w2, w2, w3, w3);
        wa4[j * 4 + 2] = make_float4(w4, w4, w5, w5);
        wa4[j * 4 + 3] = make_float4(wo, wo, hd, hd);
    }

    const float* HsT = g_HsT[rb];
    const float* AvL = g_Av[rb];
    const int sl = w * 64 + 2 * lane;
    const int sg = half * 256 + sl;

    float2 eav[ED];
#pragma unroll
    for (int k = 0; k < ED; k++)
        eav[k] = *(const float2*)(g_eaT + (size_t)k * EE + d * NN + sg);

    ea2[(sl + 0) * 3 + 0] = make_float4(eav[0].x, eav[0].x, eav[1].x, eav[1].x);
    ea2[(sl + 0) * 3 + 1] = make_float4(eav[2].x, eav[2].x, eav[3].x, eav[3].x);
    ea2[(sl + 0) * 3 + 2] = make_float4(eav[4].x, eav[4].x, eav[5].x, eav[5].x);
    ea2[(sl + 1) * 3 + 0] = make_float4(eav[0].y, eav[0].y, eav[1].y, eav[1].y);
    ea2[(sl + 1) * 3 + 1] = make_float4(eav[2].y, eav[2].y, eav[3].y, eav[3].y);
    ea2[(sl + 1) * 3 + 2] = make_float4(eav[4].y, eav[4].y, eav[5].y, eav[5].y);
    __syncthreads();

    // ---- Pass 1: attention logits for the 2 srcs, full j-loop ----
    float2 lg = make_float2(0.f, 0.f);
    const float2 c02 = make_float2(0.2f, 0.2f);
#pragma unroll 8
    for (int j = 0; j < H; j++) {
        float4 c0 = wa4[j * 4 + 0];
        float4 c1 = wa4[j * 4 + 1];
        float4 c2 = wa4[j * 4 + 2];
        float4 c3 = wa4[j * 4 + 3];
        float2 hs2 = *(const float2*)(HsT + j * NN + sg);
        float2 z  = fadd2(hs2, make_float2(c3.z, c3.w));
        float2 z2 = fmul2(eav[3], make_float2(c1.z, c1.w));
        z  = ffma2(eav[0], make_float2(c0.x, c0.y), z);
        z2 = ffma2(eav[4], make_float2(c2.x, c2.y), z2);
        z  = ffma2(eav[1], make_float2(c0.z, c0.w), z);
        z2 = ffma2(eav[5], make_float2(c2.z, c2.w), z2);
        z  = ffma2(eav[2], make_float2(c1.x, c1.y), z);
        z  = fadd2(z, z2);
        float2 s = fmul2(z, c02);
        z.x = fmaxf(z.x, s.x);
        z.y = fmaxf(z.y, s.y);
        lg = ffma2(z, make_float2(c3.x, c3.y), lg);
    }

    // ---- Per-warp register softmax over this warp's 64 srcs ----
    {
        float m = warp_max(fmaxf(lg.x, lg.y));
        float e0 = __expf(lg.x - m), e1 = __expf(lg.y - m);
        float s_w = warp_sum(e0 + e1);
        if (lane == 0) { pm[w] = m; ps[w] = s_w; }
        *(float4*)(wexp2 + sl) = make_float4(e0, e0, e1, e1);
    }
    __syncthreads();

    // ---- Pass 2: alpha-weighted value aggregation (f32x2, 2 dims/lane) ----
    const int j0 = 2 * lane;
    float2 wv[ED];
#pragma unroll
    for (int k = 0; k < ED; k++) wv[k] = *(const float2*)(valW1e + k * H + j0);

    float2 acc0 = make_float2(0.f, 0.f), acc1 = make_float2(0.f, 0.f);
    const int base = w * 64;
    const float* avbase = AvL + (size_t)(half * 256) * H + j0;
#pragma unroll 4
    for (int i = 0; i < 64; i += 2) {
#pragma unroll
        for (int u = 0; u < 2; u++) {
            int s = base + i + u;
            float4 q0 = ea2[s * 3 + 0];
            float4 q1 = ea2[s * 3 + 1];
            float4 q2 = ea2[s * 3 + 2];
            float2 p = *(const float2*)(avbase + (size_t)s * H);
            p = ffma2(make_float2(q0.x, q0.y), wv[0], p);
            p = ffma2(make_float2(q0.z, q0.w), wv[1], p);
            p = ffma2(make_float2(q1.x, q1.y), wv[2], p);
            p = ffma2(make_float2(q1.z, q1.w), wv[3], p);
            p = ffma2(make_float2(q2.x, q2.y), wv[4], p);
            p = ffma2(make_float2(q2.z, q2.w), wv[5], p);
            p.x = fmaxf(p.x, 0.f);
            p.y = fmaxf(p.y, 0.f);
            float2 wt2 = wexp2[s];
            if (u) acc1 = ffma2(wt2, p, acc1);
            else   acc0 = ffma2(wt2, p, acc0);
        }
    }
    acc0 = fadd2(acc0, acc1);
    *(float2*)(pacc + w * H + j0) = acc0;
    __syncthreads();

    // ---- Block combine 4 warp partials, write global partial ----
    if (t < H) {
        float M = fmaxf(fmaxf(pm[0], pm[1]), fmaxf(pm[2], pm[3]));
        float sc0 = __expf(pm[0] - M), sc1 = __expf(pm[1] - M);
        float sc2 = __expf(pm[2] - M), sc3 = __expf(pm[3] - M);
        float stot = ps[0] * sc0 + ps[1] * sc1 + ps[2] * sc2 + ps[3] * sc3;
        float a = pacc[0 * H + t] * sc0 + pacc[1 * H + t] * sc1
                + pacc[2 * H + t] * sc2 + pacc[3 * H + t] * sc3;
        g_pacc[bid * H + t] = a;
        if (t == 0) { g_pm[bid] = M; g_ps[bid] = stot; }
    }
}

// Node kernel: grid 512 (one dst per block), 256 threads = 8 warps (28/SM).
// Thread t: output o = t>>2, k-quarter kq = t&3. Every matvec stage is
// k-split 4 ways with intra-warp shfl_xor reduction (threads 4o..4o+3 are in
// the same warp) -> stage critical path = 16 FMA + 2 shuffles + 1 barrier.
__global__ void __launch_bounds__(256) node_kernel(
    const float* __restrict__ valW2, const float* __restrict__ valB2,
    const float* __restrict__ updW1, const float* __restrict__ updB1,
    const float* __restrict__ updW2, const float* __restrict__ updB2,
    const float* __restrict__ lng, const float* __restrict__ lnb,
    const float* __restrict__ nattW1, const float* __restrict__ nattB1,
    const float* __restrict__ nvalW1, const float* __restrict__ nvalB1,
    const float* __restrict__ decW1, const float* __restrict__ decB1,
    const float* __restrict__ decW2, const float* __restrict__ decB2,
    float* __restrict__ out, int rb, int last)
{
    const int d = blockIdx.x;
    const int t = threadIdx.x, lane = t & 31;
    const int o = t >> 2, kq = t & 3;
    const int wb = rb ^ 1;

    __shared__ float agg[H], hbuf[H], tmp[H], hid[H], rr[H], hn[H], red[4];

    // Stage 0: combine halves' softmax partials; load h
    if (t < H) {
        float m0 = g_pm[2 * d], m1 = g_pm[2 * d + 1];
        float M = fmaxf(m0, m1);
        float sc0 = __expf(m0 - M), sc1 = __expf(m1 - M);
        float stot = g_ps[2 * d] * sc0 + g_ps[2 * d + 1] * sc1;
        float a = g_pacc[(2 * d) * H + t] * sc0 + g_pacc[(2 * d + 1) * H + t] * sc1;
        agg[t] = a / stot;
        hbuf[t] = g_h[d * H + t];
    }
    __syncthreads();

    // Stage 1: tmp = val_b2 + agg @ val_w2
    {
        float p = 0.f;
        const int k0 = kq * 16;
#pragma unroll
        for (int kk = 0; kk < 16; kk++) p = fmaf(agg[k0 + kk], valW2[(k0 + kk) * H + o], p);
        p += __shfl_xor_sync(0xffffffffu, p, 1);
        p += __shfl_xor_sync(0xffffffffu, p, 2);
        if (kq == 0) tmp[o] = valB2[o] + p;
    }
    __syncthreads();

    // Stage 2: hid = relu(upd_b1 + [h,tmp] @ upd_w1)  (k in [0,128), 32 per kq)
    {
        float p = 0.f;
        const int k0 = kq * 32;
        const float* srcv = (kq < 2) ? hbuf : tmp;
        const int koff = (kq & 1) * 32;
#pragma unroll
        for (int kk = 0; kk < 32; kk++) p = fmaf(srcv[koff + kk], updW1[(k0 + kk) * H + o], p);
        p += __shfl_xor_sync(0xffffffffu, p, 1);
        p += __shfl_xor_sync(0xffffffffu, p, 2);
        if (kq == 0) hid[o] = fmaxf(updB1[o] + p, 0.f);
    }
    __syncthreads();

    // Stage 3: rr = upd_b2 + hid @ upd_w2 + h (residual)
    {
        float p = 0.f;
        const int k0 = kq * 16;
#pragma unroll
        for (int kk = 0; kk < 16; kk++) p = fmaf(hid[k0 + kk], updW2[(k0 + kk) * H + o], p);
        p += __shfl_xor_sync(0xffffffffu, p, 1);
        p += __shfl_xor_sync(0xffffffffu, p, 2);
        if (kq == 0) rr[o] = updB2[o] + p + hbuf[o];
    }
    __syncthreads();

    // LayerNorm (threads 0..63, warps 0-1; fused sum/sumsq)
    float r = 0.f;
    if (t < H) {
        r = rr[t];
        float s1 = warp_sum(r);
        float s2 = warp_sum(r * r);
        if (lane == 0) { red[t >> 5] = s1; red[(t >> 5) + 2] = s2; }
    }
    __syncthreads();
    if (t < H) {
        float mu  = (red[0] + red[1]) * (1.0f / H);
        float ex2 = (red[2] + red[3]) * (1.0f / H);
        float var = ex2 - mu * mu;
        float hnv = lng[t] * (r - mu) * rsqrtf(var + LN_EPS) + lnb[t];
        hn[t] = hnv;
        if (!last) g_h[d * H + t] = hnv;
    }
    __syncthreads();

    if (!last) {
        // Next-layer tables: 3 independent matvecs, barrier-free back-to-back
        const int k0 = kq * 16;
        float pa = 0.f, pb = 0.f, pc = 0.f;
#pragma unroll
        for (int kk = 0; kk < 16; kk++) {
            float hv = hn[k0 + kk];
            pa = fmaf(hv, nattW1[(k0 + kk) * H + o], pa);
            pb = fmaf(hv, nattW1[(H + k0 + kk) * H + o], pb);
            pc = fmaf(hv, nvalW1[(k0 + kk) * H + o], pc);
        }
        pa += __shfl_xor_sync(0xffffffffu, pa, 1);
        pa += __shfl_xor_sync(0xffffffffu, pa, 2);
        pb += __shfl_xor_sync(0xffffffffu, pb, 1);
        pb += __shfl_xor_sync(0xffffffffu, pb, 2);
        pc += __shfl_xor_sync(0xffffffffu, pc, 1);
        pc += __shfl_xor_sync(0xffffffffu, pc, 2);
        if (kq == 0) {
            g_Hd[d * H + o]       = nattB1[o] + pa;
            g_HsT[wb][o * NN + d] = pb;
            g_Av[wb][d * H + o]   = nvalB1[o] + pc;
        }
    } else {
        // Decoder: hid2 = relu(decB1 + hn @ decW1); out = decB2 + hid2 . decW2
        {
            float p = 0.f;
            const int k0 = kq * 16;
#pragma unroll
            for (int kk = 0; kk < 16; kk++) p = fmaf(hn[k0 + kk], decW1[(k0 + kk) * H + o], p);
            p += __shfl_xor_sync(0xffffffffu, p, 1);
            p += __shfl_xor_sync(0xffffffffu, p, 2);
            if (kq == 0) tmp[o] = fmaxf(decB1[o] + p, 0.f);
        }
        __syncthreads();
        if (t < H) {
            float p = tmp[t] * decW2[t];
            float psum = warp_sum(p);
            if (lane == 0) red[t >> 5] = psum;
        }
        __syncthreads();
        if (t == 0) out[d] = red[0] + red[1] + decB2[0];
    }
}

extern "C" void kernel_launch(void* const* d_in, const int* in_sizes, int n_in,
                              void* d_out, int out_size)
{
    const float* x      = (const float*)d_in[0];
    const float* ea     = (const float*)d_in[1];
    const float* enc_w1 = (const float*)d_in[2];
    const float* enc_b1 = (const float*)d_in[3];
    const float* enc_w2 = (const float*)d_in[4];
    const float* enc_b2 = (const float*)d_in[5];
    const float* att_w1 = (const float*)d_in[6];   // [4,134,64]
    const float* att_b1 = (const float*)d_in[7];   // [4,64]
    const float* att_w2 = (const float*)d_in[8];   // [4,64,1]
    // d_in[9] = att_b2 — cancels inside softmax, unused
    const float* val_w1 = (const float*)d_in[10];  // [4,70,64]
    const float* val_b1 = (const float*)d_in[11];  // [4,64]
    const float* val_w2 = (const float*)d_in[12];  // [4,64,64]
    const float* val_b2 = (const float*)d_in[13];  // [4,64]
    const float* upd_w1 = (const float*)d_in[14];  // [4,128,64]
    const float* upd_b1 = (const float*)d_in[15];  // [4,64]
    const float* upd_w2 = (const float*)d_in[16];  // [4,64,64]
    const float* upd_b2 = (const float*)d_in[17];  // [4,64]
    const float* ln_g   = (const float*)d_in[18];  // [4,64]
    const float* ln_b   = (const float*)d_in[19];  // [4,64]
    const float* dec_w1 = (const float*)d_in[20];
    const float* dec_b1 = (const float*)d_in[21];
    const float* dec_w2 = (const float*)d_in[22];
    const float* dec_b2 = (const float*)d_in[23];
    // d_in[24] = edge_index: src=e/512, dst=e%512 (structure exploited directly)

    float* out = (float*)d_out;

    ea_transpose_kernel<<<dim3(16, 16), 256>>>(ea);
    enc_kernel<<<NN, H>>>(x, enc_w1, enc_b1, enc_w2, enc_b2,
                          att_w1, att_b1, val_w1, val_b1);

    for (int l = 0; l < NL; l++) {
        int last = (l == NL - 1);
        int nl = (l + 1) % NL;      // dummy-but-valid pointers on last layer
        int rb = l & 1;             // enc wrote buffer 0; layer l reads l&1, writes (l&1)^1
        edge_kernel<<<2 * NN, 128>>>(att_w1 + (l * 134 + 128) * H,
                                     att_w2 + l * H,
                                     val_w1 + (l * 70 + 64) * H,
                                     rb);
        node_kernel<<<NN, 256>>>(val_w2 + l * H * H, val_b2 + l * H,
                                 upd_w1 + l * 2 * H * H, upd_b1 + l * H,
                                 upd_w2 + l * H * H, upd_b2 + l * H,
                                 ln_g + l * H, ln_b + l * H,
                                 att_w1 + nl * 134 * H, att_b1 + nl * H,
                                 val_w1 + nl * 70 * H, val_b1 + nl * H,
                                 dec_w1, dec_b1, dec_w2, dec_b2,
                                 out, rb, last);
    }
}

// round 16
// speedup vs baseline: 1.1642x; 1.1642x over previous
#include <cuda_runtime.h>
#include <string.h>

#define NN 512
#define H  64
#define ED 6
#define NL 4
#define EE (NN*NN)
#define LN_EPS 1e-5f

// Scratch (device globals: no allocations allowed)
__device__ float g_h  [NN*H];
__device__ float g_Hd [NN*H];         // dst-side attention proj (+att_b1), row-major
__device__ float g_HsT[2][H*NN];      // src-side attention proj, DIM-MAJOR [j][s], double buffered
__device__ float g_Av [2][NN*H];      // src-side value proj (+val_b1), row-major, double buffered
__device__ float g_eaT[ED*EE];        // edge_attr transposed: eaT[k][d][s]

__device__ __forceinline__ float warp_sum(float v) {
#pragma unroll
    for (int o = 16; o; o >>= 1) v += __shfl_xor_sync(0xffffffffu, v, o);
    return v;
}
__device__ __forceinline__ float warp_max(float v) {
#pragma unroll
    for (int o = 16; o; o >>= 1) v = fmaxf(v, __shfl_xor_sync(0xffffffffu, v, o));
    return v;
}

// Packed fp32x2 ops (sm_103a): 2 fp32 FMAs per instruction
__device__ __forceinline__ float2 ffma2(float2 a, float2 b, float2 c) {
    unsigned long long ua, ub, uc, ur;
    memcpy(&ua, &a, 8); memcpy(&ub, &b, 8); memcpy(&uc, &c, 8);
    asm("fma.rn.f32x2 %0, %1, %2, %3;" : "=l"(ur) : "l"(ua), "l"(ub), "l"(uc));
    float2 r; memcpy(&r, &ur, 8); return r;
}
__device__ __forceinline__ float2 fadd2(float2 a, float2 b) {
    unsigned long long ua, ub, ur;
    memcpy(&ua, &a, 8); memcpy(&ub, &b, 8);
    asm("add.rn.f32x2 %0, %1, %2;" : "=l"(ur) : "l"(ua), "l"(ub));
    float2 r; memcpy(&r, &ur, 8); return r;
}
__device__ __forceinline__ float2 fmul2(float2 a, float2 b) {
    unsigned long long ua, ub, ur;
    memcpy(&ua, &a, 8); memcpy(&ub, &b, 8);
    asm("mul.rn.f32x2 %0, %1, %2;" : "=l"(ur) : "l"(ua), "l"(ub));
    float2 r; memcpy(&r, &ur, 8); return r;
}
__device__ __forceinline__ float2 dup2(float v) { return make_float2(v, v); }

// Per-node tables: Hd = h@Wa[0:64]+b1a (row), HsT = h@Wa[64:128] (dim-major), Av = h@Wv[0:64]+b1v (row)
__device__ __forceinline__ void compute_tables(
    int d, int t, int wb, const float* h_sh,
    const float* __restrict__ attW1, const float* __restrict__ attB1,
    const float* __restrict__ valW1, const float* __restrict__ valB1)
{
    float ad = attB1[t], as = 0.f, av = valB1[t];
#pragma unroll 8
    for (int k = 0; k < H; k++) {
        float hk = h_sh[k];
        ad += hk * attW1[k * H + t];
        as += hk * attW1[(H + k) * H + t];
        av += hk * valW1[k * H + t];
    }
    g_Hd[d * H + t]       = ad;
    g_HsT[wb][t * NN + d] = as;
    g_Av[wb][d * H + t]   = av;
}

// Transpose edge_attr: ea[s][d][k] -> eaT[k][d][s]. grid (16,16), block 256.
__global__ void __launch_bounds__(256) ea_transpose_kernel(const float* __restrict__ ea)
{
    __shared__ float t_sh[ED][32][33];
    const int t = threadIdx.x, w = t >> 5, lane = t & 31;
    const int bs = blockIdx.x * 32, bd = blockIdx.y * 32;

#pragma unroll
    for (int rr = 0; rr < 4; rr++) {
        int s_loc = w + rr * 8;
        const float* base = ea + ((size_t)(bs + s_loc) * NN + bd) * ED + lane * ED;
        float2 v0 = *(const float2*)(base);
        float2 v1 = *(const float2*)(base + 2);
        float2 v2 = *(const float2*)(base + 4);
        t_sh[0][lane][s_loc] = v0.x; t_sh[1][lane][s_loc] = v0.y;
        t_sh[2][lane][s_loc] = v1.x; t_sh[3][lane][s_loc] = v1.y;
        t_sh[4][lane][s_loc] = v2.x; t_sh[5][lane][s_loc] = v2.y;
    }
    __syncthreads();
#pragma unroll
    for (int idx = t; idx < ED * 32 * 32; idx += 256) {
        int k = idx >> 10, r = idx & 1023, dl = r >> 5, sl = r & 31;
        g_eaT[(size_t)k * EE + (size_t)(bd + dl) * NN + bs + sl] = t_sh[k][dl][sl];
    }
}

// Encoder: h = relu(x@W1+b1)@W2+b2, then layer-0 tables (buffer 0). grid=512, block=64
__global__ void __launch_bounds__(H) enc_kernel(
    const float* __restrict__ x,
    const float* __restrict__ ew1, const float* __restrict__ eb1,
    const float* __restrict__ ew2, const float* __restrict__ eb2,
    const float* __restrict__ attW1, const float* __restrict__ attB1,
    const float* __restrict__ valW1, const float* __restrict__ valB1)
{
    int d = blockIdx.x, t = threadIdx.x;
    __shared__ float xs[ED], hid[H], hsn[H];
    if (t < ED) xs[t] = x[d * ED + t];
    __syncthreads();
    float a = eb1[t];
#pragma unroll
    for (int k = 0; k < ED; k++) a += xs[k] * ew1[k * H + t];
    hid[t] = fmaxf(a, 0.f);
    __syncthreads();
    float hv = eb2[t];
#pragma unroll 8
    for (int k = 0; k < H; k++) hv += hid[k] * ew2[k * H + t];
    g_h[d * H + t] = hv;
    hsn[t] = hv;
    __syncthreads();
    compute_tables(d, t, 0, hsn, attW1, attB1, valW1, valB1);
}

// Fused layer (R6 champion shape): one block per dst d. 128 threads = 4 warps;
// warp w owns srcs [w*128, w*128+128); lane owns 4 srcs. Pass-1 weight table
// PRE-DUPLICATED in smem (4 LDS.128/j, pairs extracted as register aliases —
// no dup MOVs). Pass 2 unchanged from R6 (non-dup ea + dup2 MOVs) except
// softmax weights fetched as float4 per 4 srcs.
__global__ void __launch_bounds__(128, 6) layer_kernel(
    const float* __restrict__ attW1e,   // [6,64] edge rows of att_w1[l]
    const float* __restrict__ attW2,    // [64]
    const float* __restrict__ valW1e,   // [6,64] edge rows of val_w1[l]
    const float* __restrict__ valW2, const float* __restrict__ valB2,
    const float* __restrict__ updW1, const float* __restrict__ updB1,
    const float* __restrict__ updW2, const float* __restrict__ updB2,
    const float* __restrict__ lng, const float* __restrict__ lnb,
    const float* __restrict__ nattW1, const float* __restrict__ nattB1,
    const float* __restrict__ nvalW1, const float* __restrict__ nvalB1,
    const float* __restrict__ decW1, const float* __restrict__ decB1,
    const float* __restrict__ decW2, const float* __restrict__ decB2,
    float* __restrict__ out, int rb, int last)
{
    const int d = blockIdx.x;
    const int t = threadIdx.x, w = t >> 5, lane = t & 31;
    const int wb = rb ^ 1;

    __shared__ __align__(16) float4 wa4[H * 4];  // per j: (w0,w0,w1,w1)(w2,w2,w3,w3)(w4,w4,w5,w5)(wo,wo,hd,hd)
    __shared__ __align__(16) float4 eaA[NN];     // per s: (e0,e1,e2,e3)
    __shared__ __align__(16) float2 eaB[NN];     // per s: (e4,e5)
    __shared__ float  wexp[NN];                  // softmax weights
    __shared__ float  pm[4], ps[4], pacc[4 * H];
    __shared__ float  part2[2 * H], agg_sh[H], h_sh[H], tmp_sh[H], hid_sh[H], hn_sh[H], red_sh[4];

    // Prologue: duplicated weight table + Hd row
    if (t < H) {
        int j = t;
        float w0 = attW1e[0 * H + j], w1 = attW1e[1 * H + j];
        float w2 = attW1e[2 * H + j], w3 = attW1e[3 * H + j];
        float w4 = attW1e[4 * H + j], w5 = attW1e[5 * H + j];
        float wo = attW2[j];
        float hd = g_Hd[d * H + j];
        wa4[j * 4 + 0] = make_float4(w0, w0, w1, w1);
        wa4[j * 4 + 1] = make_float4(w2, w2, w3, w3);
        wa4[j * 4 + 2] = make_float4(w4, w4, w5, w5);
        wa4[j * 4 + 3] = make_float4(wo, wo, hd, hd);
    }

    const float* HsT = g_HsT[rb];
    const float* AvL = g_Av[rb];
    const int sa = w * 128 + 4 * lane;   // 4 srcs: sa..sa+3

    // Load ea for the 4 srcs (float4 from eaT, contiguous) — registers
    float4 eaq[ED];
#pragma unroll
    for (int k = 0; k < ED; k++)
        eaq[k] = *(const float4*)(g_eaT + (size_t)k * EE + d * NN + sa);

    // Publish packed (non-duplicated) ea for pass 2
#pragma unroll
    for (int u = 0; u < 4; u++) {
        float e0 = (u == 0) ? eaq[0].x : (u == 1) ? eaq[0].y : (u == 2) ? eaq[0].z : eaq[0].w;
        float e1 = (u == 0) ? eaq[1].x : (u == 1) ? eaq[1].y : (u == 2) ? eaq[1].z : eaq[1].w;
        float e2 = (u == 0) ? eaq[2].x : (u == 1) ? eaq[2].y : (u == 2) ? eaq[2].z : eaq[2].w;
        float e3 = (u == 0) ? eaq[3].x : (u == 1) ? eaq[3].y : (u == 2) ? eaq[3].z : eaq[3].w;
        float e4 = (u == 0) ? eaq[4].x : (u == 1) ? eaq[4].y : (u == 2) ? eaq[4].z : eaq[4].w;
        float e5 = (u == 0) ? eaq[5].x : (u == 1) ? eaq[5].y : (u == 2) ? eaq[5].z : eaq[5].w;
        eaA[sa + u] = make_float4(e0, e1, e2, e3);
        eaB[sa + u] = make_float2(e4, e5);
    }

    // Src pairs for f32x2: A = (sa, sa+1), B = (sa+2, sa+3)  (register aliases)
    float2 eA[ED], eB[ED];
#pragma unroll
    for (int k = 0; k < ED; k++) {
        eA[k] = make_float2(eaq[k].x, eaq[k].y);
        eB[k] = make_float2(eaq[k].z, eaq[k].w);
    }
    __syncthreads();

    // ---- Pass 1: attention logits, full j-loop; dup weights via LDS.128 ----
    float2 lgA = make_float2(0.f, 0.f), lgB = make_float2(0.f, 0.f);
    const float2 c02 = make_float2(0.2f, 0.2f);
#pragma unroll 8
    for (int j = 0; j < H; j++) {
        float4 c0 = wa4[j * 4 + 0];
        float4 c1 = wa4[j * 4 + 1];
        float4 c2 = wa4[j * 4 + 2];
        float4 c3 = wa4[j * 4 + 3];
        float4 hs4 = *(const float4*)(HsT + j * NN + sa);
        float2 HD = make_float2(c3.z, c3.w);
        float2 Wo = make_float2(c3.x, c3.y);
        // two 3-deep chains per src pair (4 independent chains)
        float2 zA  = fadd2(make_float2(hs4.x, hs4.y), HD);
        float2 zB  = fadd2(make_float2(hs4.z, hs4.w), HD);
        float2 zA2 = fmul2(eA[3], make_float2(c1.z, c1.w));
        float2 zB2 = fmul2(eB[3], make_float2(c1.z, c1.w));
        zA  = ffma2(eA[0], make_float2(c0.x, c0.y), zA);
        zB  = ffma2(eB[0], make_float2(c0.x, c0.y), zB);
        zA2 = ffma2(eA[4], make_float2(c2.x, c2.y), zA2);
        zB2 = ffma2(eB[4], make_float2(c2.x, c2.y), zB2);
        zA  = ffma2(eA[1], make_float2(c0.z, c0.w), zA);
        zB  = ffma2(eB[1], make_float2(c0.z, c0.w), zB);
        zA2 = ffma2(eA[5], make_float2(c2.z, c2.w), zA2);
        zB2 = ffma2(eB[5], make_float2(c2.z, c2.w), zB2);
        zA  = ffma2(eA[2], make_float2(c1.x, c1.y), zA);
        zB  = ffma2(eB[2], make_float2(c1.x, c1.y), zB);
        zA  = fadd2(zA, zA2);
        zB  = fadd2(zB, zB2);
        // leaky_relu(., 0.2)
        float2 sA = fmul2(zA, c02);
        float2 sB = fmul2(zB, c02);
        zA.x = fmaxf(zA.x, sA.x); zA.y = fmaxf(zA.y, sA.y);
        zB.x = fmaxf(zB.x, sB.x); zB.y = fmaxf(zB.y, sB.y);
        lgA = ffma2(zA, Wo, lgA);
        lgB = ffma2(zB, Wo, lgB);
    }

    // ---- Per-warp register softmax over this warp's 128 srcs ----
    {
        float m = warp_max(fmaxf(fmaxf(lgA.x, lgA.y), fmaxf(lgB.x, lgB.y)));
        float e0 = __expf(lgA.x - m), e1 = __expf(lgA.y - m);
        float e2 = __expf(lgB.x - m), e3 = __expf(lgB.y - m);
        float s_w = warp_sum(e0 + e1 + e2 + e3);
        if (lane == 0) { pm[w] = m; ps[w] = s_w; }
        *(float4*)(wexp + sa) = make_float4(e0, e1, e2, e3);
    }
    __syncthreads();

    // ---- Pass 2: alpha-weighted value aggregation (f32x2, 2 dims/lane) ----
    const int j0 = 2 * lane;
    float2 wv[ED];
#pragma unroll
    for (int k = 0; k < ED; k++) wv[k] = *(const float2*)(valW1e + k * H + j0);

    float2 acc0 = make_float2(0.f, 0.f), acc1 = make_float2(0.f, 0.f);
    const int s0 = w * 128;
#pragma unroll 2
    for (int i = 0; i < 128; i += 4) {
        float4 wg4 = *(const float4*)(wexp + s0 + i);
#pragma unroll
        for (int u = 0; u < 4; u++) {
            int s = s0 + i + u;
            float4 dA = eaA[s];
            float2 dB = eaB[s];
            float2 p = *(const float2*)(AvL + (size_t)s * H + j0);
            p = ffma2(dup2(dA.x), wv[0], p);
            p = ffma2(dup2(dA.y), wv[1], p);
            p = ffma2(dup2(dA.z), wv[2], p);
            p = ffma2(dup2(dA.w), wv[3], p);
            p = ffma2(dup2(dB.x), wv[4], p);
            p = ffma2(dup2(dB.y), wv[5], p);
            p.x = fmaxf(p.x, 0.f);
            p.y = fmaxf(p.y, 0.f);
            float wt = (u == 0) ? wg4.x : (u == 1) ? wg4.y : (u == 2) ? wg4.z : wg4.w;
            if (u & 1) acc1 = ffma2(dup2(wt), p, acc1);
            else       acc0 = ffma2(dup2(wt), p, acc0);
        }
    }
    acc0 = fadd2(acc0, acc1);
    *(float2*)(pacc + w * H + j0) = acc0;
    __syncthreads();

    // ---- Combine 4 warp softmax partials ----
    if (t < H) {
        float M = fmaxf(fmaxf(pm[0], pm[1]), fmaxf(pm[2], pm[3]));
        float sc0 = __expf(pm[0] - M), sc1 = __expf(pm[1] - M);
        float sc2 = __expf(pm[2] - M), sc3 = __expf(pm[3] - M);
        float stot = ps[0] * sc0 + ps[1] * sc1 + ps[2] * sc2 + ps[3] * sc3;
        float a = pacc[0 * H + t] * sc0 + pacc[1 * H + t] * sc1
                + pacc[2 * H + t] * sc2 + pacc[3 * H + t] * sc3;
        agg_sh[t] = a / stot;
        h_sh[t]   = g_h[d * H + t];
    }
    __syncthreads();

    // ---- Node phase, 2-way k-split matvecs over 128 threads ----
    const int o = t & 63, q = t >> 6;

    // stage 1: tmp = val_b2 + agg @ val_w2
    {
        float p = 0.f;
        int k0 = q * 32;
#pragma unroll
        for (int kk = 0; kk < 32; kk++) p += agg_sh[k0 + kk] * valW2[(k0 + kk) * H + o];
        part2[q * H + o] = p;
    }
    __syncthreads();
    if (t < H) tmp_sh[t] = valB2[t] + part2[t] + part2[H + t];
    __syncthreads();

    // stage 2: hid = relu(upd_b1 + [h,tmp] @ upd_w1)
    {
        const float* srcv = (q == 0) ? h_sh : tmp_sh;
        int rbase = q * H;
        float p = 0.f;
#pragma unroll
        for (int kk = 0; kk < 64; kk++) p += srcv[kk] * updW1[(rbase + kk) * H + o];
        part2[q * H + o] = p;
    }
    __syncthreads();
    if (t < H) hid_sh[t] = fmaxf(updB1[t] + part2[t] + part2[H + t], 0.f);
    __syncthreads();

    // stage 3: u = upd_b2 + hid @ upd_w2
    {
        float p = 0.f;
        int k0 = q * 32;
#pragma unroll
        for (int kk = 0; kk < 32; kk++) p += hid_sh[k0 + kk] * updW2[(k0 + kk) * H + o];
        part2[q * H + o] = p;
    }
    __syncthreads();

    // residual + LayerNorm (threads 0..63 = warps 0,1; fused sum/sumsq)
    float r = 0.f, dr = 0.f;
    if (t < H) {
        float u = updB2[t] + part2[t] + part2[H + t];
        r = u + h_sh[t];
        float s1 = warp_sum(r);
        float s2 = warp_sum(r * r);
        if (lane == 0) { red_sh[w] = s1; red_sh[w + 2] = s2; }
    }
    __syncthreads();
    if (t < H) {
        float mu  = (red_sh[0] + red_sh[1]) * (1.0f / H);
        float ex2 = (red_sh[2] + red_sh[3]) * (1.0f / H);
        float var = ex2 - mu * mu;
        dr = r - mu;
        float hn = lng[t] * dr * rsqrtf(var + LN_EPS) + lnb[t];
        hn_sh[t] = hn;
        if (!last) g_h[d * H + t] = hn;
    }
    __syncthreads();

    if (!last) {
        if (t < H)
            compute_tables(d, t, wb, hn_sh, nattW1, nattB1, nvalW1, nvalB1);
    } else {
        if (t < H) {
            float dh = decB1[t];
#pragma unroll 8
            for (int k = 0; k < H; k++) dh += hn_sh[k] * decW1[k * H + t];
            dh = fmaxf(dh, 0.f);
            float p = dh * decW2[t];
            float psum = warp_sum(p);
            if (lane == 0) red_sh[w] = psum;
        }
        __syncthreads();
        if (t == 0) out[d] = red_sh[0] + red_sh[1] + decB2[0];
    }
}

extern "C" void kernel_launch(void* const* d_in, const int* in_sizes, int n_in,
                              void* d_out, int out_size)
{
    const float* x      = (const float*)d_in[0];
    const float* ea     = (const float*)d_in[1];
    const float* enc_w1 = (const float*)d_in[2];
    const float* enc_b1 = (const float*)d_in[3];
    const float* enc_w2 = (const float*)d_in[4];
    const float* enc_b2 = (const float*)d_in[5];
    const float* att_w1 = (const float*)d_in[6];   // [4,134,64]
    const float* att_b1 = (const float*)d_in[7];   // [4,64]
    const float* att_w2 = (const float*)d_in[8];   // [4,64,1]
    // d_in[9] = att_b2 — cancels inside softmax, unused
    const float* val_w1 = (const float*)d_in[10];  // [4,70,64]
    const float* val_b1 = (const float*)d_in[11];  // [4,64]
    const float* val_w2 = (const float*)d_in[12];  // [4,64,64]
    const float* val_b2 = (const float*)d_in[13];  // [4,64]
    const float* upd_w1 = (const float*)d_in[14];  // [4,128,64]
    const float* upd_b1 = (const float*)d_in[15];  // [4,64]
    const float* upd_w2 = (const float*)d_in[16];  // [4,64,64]
    const float* upd_b2 = (const float*)d_in[17];  // [4,64]
    const float* ln_g   = (const float*)d_in[18];  // [4,64]
    const float* ln_b   = (const float*)d_in[19];  // [4,64]
    const float* dec_w1 = (const float*)d_in[20];
    const float* dec_b1 = (const float*)d_in[21];
    const float* dec_w2 = (const float*)d_in[22];
    const float* dec_b2 = (const float*)d_in[23];
    // d_in[24] = edge_index: src=e/512, dst=e%512 (structure exploited directly)

    float* out = (float*)d_out;

    ea_transpose_kernel<<<dim3(16, 16), 256>>>(ea);
    enc_kernel<<<NN, H>>>(x, enc_w1, enc_b1, enc_w2, enc_b2,
                          att_w1, att_b1, val_w1, val_b1);

    for (int l = 0; l < NL; l++) {
        int last = (l == NL - 1);
        int nl = (l + 1) % NL;      // dummy-but-valid pointers on last layer
        int rb = l & 1;             // enc wrote buffer 0; layer l reads l&1, writes (l&1)^1
        layer_kernel<<<NN, 128>>>(att_w1 + (l * 134 + 128) * H,
                                  att_w2 + l * H,
                                  val_w1 + (l * 70 + 64) * H,
                                  val_w2 + l * H * H, val_b2 + l * H,
                                  upd_w1 + l * 2 * H * H, upd_b1 + l * H,
                                  upd_w2 + l * H * H, upd_b2 + l * H,
                                  ln_g + l * H, ln_b + l * H,
                                  att_w1 + nl * 134 * H, att_b1 + nl * H,
                                  val_w1 + nl * 70 * H, val_b1 + nl * H,
                                  dec_w1, dec_b1, dec_w2, dec_b2,
                                  out, rb, last);
    }
}

// round 17
// speedup vs baseline: 1.4854x; 1.2759x over previous
#include <cuda_runtime.h>
#include <string.h>

#define NN 512
#define H  64
#define ED 6
#define NL 4
#define EE (NN*NN)
#define LN_EPS 1e-5f

// Scratch (device globals: no allocations allowed)
__device__ float g_h  [NN*H];
__device__ float g_Hd [NN*H];         // dst-side attention proj (+att_b1), row-major
__device__ float g_HsT[2][H*NN];      // src-side attention proj, DIM-MAJOR [j][s], double buffered
__device__ float g_Av [2][NN*H];      // src-side value proj (+val_b1), row-major, double buffered
__device__ float g_eaT[ED*EE];        // edge_attr transposed: eaT[k][d][s]

__device__ __forceinline__ float warp_sum(float v) {
#pragma unroll
    for (int o = 16; o; o >>= 1) v += __shfl_xor_sync(0xffffffffu, v, o);
    return v;
}
__device__ __forceinline__ float warp_max(float v) {
#pragma unroll
    for (int o = 16; o; o >>= 1) v = fmaxf(v, __shfl_xor_sync(0xffffffffu, v, o));
    return v;
}

// Packed fp32x2 ops (sm_103a): 2 fp32 FMAs per instruction
__device__ __forceinline__ float2 ffma2(float2 a, float2 b, float2 c) {
    unsigned long long ua, ub, uc, ur;
    memcpy(&ua, &a, 8); memcpy(&ub, &b, 8); memcpy(&uc, &c, 8);
    asm("fma.rn.f32x2 %0, %1, %2, %3;" : "=l"(ur) : "l"(ua), "l"(ub), "l"(uc));
    float2 r; memcpy(&r, &ur, 8); return r;
}
__device__ __forceinline__ float2 fadd2(float2 a, float2 b) {
    unsigned long long ua, ub, ur;
    memcpy(&ua, &a, 8); memcpy(&ub, &b, 8);
    asm("add.rn.f32x2 %0, %1, %2;" : "=l"(ur) : "l"(ua), "l"(ub));
    float2 r; memcpy(&r, &ur, 8); return r;
}
__device__ __forceinline__ float2 fmul2(float2 a, float2 b) {
    unsigned long long ua, ub, ur;
    memcpy(&ua, &a, 8); memcpy(&ub, &b, 8);
    asm("mul.rn.f32x2 %0, %1, %2;" : "=l"(ur) : "l"(ua), "l"(ub));
    float2 r; memcpy(&r, &ur, 8); return r;
}
__device__ __forceinline__ float2 dup2(float v) { return make_float2(v, v); }

// Per-node tables: Hd = h@Wa[0:64]+b1a (row), HsT = h@Wa[64:128] (dim-major), Av = h@Wv[0:64]+b1v (row)
__device__ __forceinline__ void compute_tables(
    int d, int t, int wb, const float* h_sh,
    const float* __restrict__ attW1, const float* __restrict__ attB1,
    const float* __restrict__ valW1, const float* __restrict__ valB1)
{
    float ad = attB1[t], as = 0.f, av = valB1[t];
#pragma unroll 8
    for (int k = 0; k < H; k++) {
        float hk = h_sh[k];
        ad += hk * attW1[k * H + t];
        as += hk * attW1[(H + k) * H + t];
        av += hk * valW1[k * H + t];
    }
    g_Hd[d * H + t]       = ad;
    g_HsT[wb][t * NN + d] = as;
    g_Av[wb][d * H + t]   = av;
}

// Transpose edge_attr: ea[s][d][k] -> eaT[k][d][s]. grid (16,16), block 256.
__global__ void __launch_bounds__(256) ea_transpose_kernel(const float* __restrict__ ea)
{
    __shared__ float t_sh[ED][32][33];
    const int t = threadIdx.x, w = t >> 5, lane = t & 31;
    const int bs = blockIdx.x * 32, bd = blockIdx.y * 32;

#pragma unroll
    for (int rr = 0; rr < 4; rr++) {
        int s_loc = w + rr * 8;
        const float* base = ea + ((size_t)(bs + s_loc) * NN + bd) * ED + lane * ED;
        float2 v0 = *(const float2*)(base);
        float2 v1 = *(const float2*)(base + 2);
        float2 v2 = *(const float2*)(base + 4);
        t_sh[0][lane][s_loc] = v0.x; t_sh[1][lane][s_loc] = v0.y;
        t_sh[2][lane][s_loc] = v1.x; t_sh[3][lane][s_loc] = v1.y;
        t_sh[4][lane][s_loc] = v2.x; t_sh[5][lane][s_loc] = v2.y;
    }
    __syncthreads();
#pragma unroll
    for (int idx = t; idx < ED * 32 * 32; idx += 256) {
        int k = idx >> 10, r = idx & 1023, dl = r >> 5, sl = r & 31;
        g_eaT[(size_t)k * EE + (size_t)(bd + dl) * NN + bs + sl] = t_sh[k][dl][sl];
    }
}

// Encoder: h = relu(x@W1+b1)@W2+b2, then layer-0 tables (buffer 0). grid=512, block=64
__global__ void __launch_bounds__(H) enc_kernel(
    const float* __restrict__ x,
    const float* __restrict__ ew1, const float* __restrict__ eb1,
    const float* __restrict__ ew2, const float* __restrict__ eb2,
    const float* __restrict__ attW1, const float* __restrict__ attB1,
    const float* __restrict__ valW1, const float* __restrict__ valB1)
{
    int d = blockIdx.x, t = threadIdx.x;
    __shared__ float xs[ED], hid[H], hsn[H];
    if (t < ED) xs[t] = x[d * ED + t];
    __syncthreads();
    float a = eb1[t];
#pragma unroll
    for (int k = 0; k < ED; k++) a += xs[k] * ew1[k * H + t];
    hid[t] = fmaxf(a, 0.f);
    __syncthreads();
    float hv = eb2[t];
#pragma unroll 8
    for (int k = 0; k < H; k++) hv += hid[k] * ew2[k * H + t];
    g_h[d * H + t] = hv;
    hsn[t] = hv;
    __syncthreads();
    compute_tables(d, t, 0, hsn, attW1, attB1, valW1, valB1);
}

// Fused layer: TWO independent R6-blocks packed per 256-thread block.
// Group g = t>>7 handles dst (2*bid+g) with its own 128 threads = 4 warps;
// per-group instruction stream identical to the R6 champion (4 srcs/lane,
// non-dup weight tables, dup2 in loops). Doubles resident warps/SM to ~28
// with zero instruction change. __syncthreads() barrier counts match across
// groups (no divergent barriers).
__global__ void __launch_bounds__(256, 2) layer_kernel(
    const float* __restrict__ attW1e,   // [6,64] edge rows of att_w1[l]
    const float* __restrict__ attW2,    // [64]
    const float* __restrict__ valW1e,   // [6,64] edge rows of val_w1[l]
    const float* __restrict__ valW2, const float* __restrict__ valB2,
    const float* __restrict__ updW1, const float* __restrict__ updB1,
    const float* __restrict__ updW2, const float* __restrict__ updB2,
    const float* __restrict__ lng, const float* __restrict__ lnb,
    const float* __restrict__ nattW1, const float* __restrict__ nattB1,
    const float* __restrict__ nvalW1, const float* __restrict__ nvalB1,
    const float* __restrict__ decW1, const float* __restrict__ decB1,
    const float* __restrict__ decW2, const float* __restrict__ decB2,
    float* __restrict__ out, int rb, int last)
{
    const int g  = threadIdx.x >> 7;          // group 0/1
    const int tl = threadIdx.x & 127;         // thread-in-group (R6's "t")
    const int d  = blockIdx.x * 2 + g;
    const int w = tl >> 5, lane = tl & 31;
    const int wb = rb ^ 1;

    __shared__ __align__(16) float4 waA[2][H];      // per j: (w0,w1,w2,w3)
    __shared__ __align__(16) float4 waB[2][H];      // per j: (w4,w5,wo,hd)
    __shared__ __align__(16) float4 eaA[2][NN];     // per s: (e0,e1,e2,e3)
    __shared__ __align__(16) float2 eaB[2][NN];     // per s: (e4,e5)
    __shared__ float  wexp[2][NN];                  // softmax weights
    __shared__ float  pm[2][4], ps[2][4], pacc[2][4 * H];
    __shared__ float  part2[2][2 * H], agg_sh[2][H], h_sh[2][H], tmp_sh[2][H];
    __shared__ float  hid_sh[2][H], hn_sh[2][H], red_sh[2][4];

    // Prologue: weight table (non-duplicated) + Hd row
    if (tl < H) {
        int j = tl;
        waA[g][j] = make_float4(attW1e[0 * H + j], attW1e[1 * H + j],
                                attW1e[2 * H + j], attW1e[3 * H + j]);
        waB[g][j] = make_float4(attW1e[4 * H + j], attW1e[5 * H + j],
                                attW2[j], g_Hd[d * H + j]);
    }

    const float* HsT = g_HsT[rb];
    const float* AvL = g_Av[rb];
    const int sa = w * 128 + 4 * lane;   // 4 srcs: sa..sa+3

    // Load ea for the 4 srcs (float4 from eaT, contiguous) — registers
    float4 eaq[ED];
#pragma unroll
    for (int k = 0; k < ED; k++)
        eaq[k] = *(const float4*)(g_eaT + (size_t)k * EE + d * NN + sa);

    // Publish packed (non-duplicated) ea for pass 2
#pragma unroll
    for (int u = 0; u < 4; u++) {
        float e0 = (u == 0) ? eaq[0].x : (u == 1) ? eaq[0].y : (u == 2) ? eaq[0].z : eaq[0].w;
        float e1 = (u == 0) ? eaq[1].x : (u == 1) ? eaq[1].y : (u == 2) ? eaq[1].z : eaq[1].w;
        float e2 = (u == 0) ? eaq[2].x : (u == 1) ? eaq[2].y : (u == 2) ? eaq[2].z : eaq[2].w;
        float e3 = (u == 0) ? eaq[3].x : (u == 1) ? eaq[3].y : (u == 2) ? eaq[3].z : eaq[3].w;
        float e4 = (u == 0) ? eaq[4].x : (u == 1) ? eaq[4].y : (u == 2) ? eaq[4].z : eaq[4].w;
        float e5 = (u == 0) ? eaq[5].x : (u == 1) ? eaq[5].y : (u == 2) ? eaq[5].z : eaq[5].w;
        eaA[g][sa + u] = make_float4(e0, e1, e2, e3);
        eaB[g][sa + u] = make_float2(e4, e5);
    }

    // Src pairs for f32x2: A = (sa, sa+1), B = (sa+2, sa+3)  (register aliases)
    float2 eA[ED], eB[ED];
#pragma unroll
    for (int k = 0; k < ED; k++) {
        eA[k] = make_float2(eaq[k].x, eaq[k].y);
        eB[k] = make_float2(eaq[k].z, eaq[k].w);
    }
    __syncthreads();

    // ---- Pass 1: attention logits, full j-loop ----
    float2 lgA = make_float2(0.f, 0.f), lgB = make_float2(0.f, 0.f);
    const float2 c02 = make_float2(0.2f, 0.2f);
#pragma unroll 8
    for (int j = 0; j < H; j++) {
        float4 wAv = waA[g][j];
        float4 wBv = waB[g][j];
        float4 hs4 = *(const float4*)(HsT + j * NN + sa);
        float2 W0 = dup2(wAv.x), W1 = dup2(wAv.y), W2 = dup2(wAv.z), W3 = dup2(wAv.w);
        float2 W4 = dup2(wBv.x), W5 = dup2(wBv.y), Wo = dup2(wBv.z), HD = dup2(wBv.w);
        // split z into two 3-deep chains per src pair (4 independent chains)
        float2 zA  = fadd2(make_float2(hs4.x, hs4.y), HD);
        float2 zB  = fadd2(make_float2(hs4.z, hs4.w), HD);
        float2 zA2 = fmul2(eA[3], W3);
        float2 zB2 = fmul2(eB[3], W3);
        zA  = ffma2(eA[0], W0, zA);   zB  = ffma2(eB[0], W0, zB);
        zA2 = ffma2(eA[4], W4, zA2);  zB2 = ffma2(eB[4], W4, zB2);
        zA  = ffma2(eA[1], W1, zA);   zB  = ffma2(eB[1], W1, zB);
        zA2 = ffma2(eA[5], W5, zA2);  zB2 = ffma2(eB[5], W5, zB2);
        zA  = ffma2(eA[2], W2, zA);   zB  = ffma2(eB[2], W2, zB);
        zA  = fadd2(zA, zA2);         zB  = fadd2(zB, zB2);
        // leaky_relu(., 0.2)
        float2 sA = fmul2(zA, c02);
        float2 sB = fmul2(zB, c02);
        zA.x = fmaxf(zA.x, sA.x); zA.y = fmaxf(zA.y, sA.y);
        zB.x = fmaxf(zB.x, sB.x); zB.y = fmaxf(zB.y, sB.y);
        lgA = ffma2(zA, Wo, lgA);
        lgB = ffma2(zB, Wo, lgB);
    }

    // ---- Per-warp register softmax over this warp's 128 srcs ----
    {
        float m = warp_max(fmaxf(fmaxf(lgA.x, lgA.y), fmaxf(lgB.x, lgB.y)));
        float e0 = __expf(lgA.x - m), e1 = __expf(lgA.y - m);
        float e2 = __expf(lgB.x - m), e3 = __expf(lgB.y - m);
        float s_w = warp_sum(e0 + e1 + e2 + e3);
        if (lane == 0) { pm[g][w] = m; ps[g][w] = s_w; }
        *(float4*)(wexp[g] + sa) = make_float4(e0, e1, e2, e3);
    }
    __syncthreads();

    // ---- Pass 2: alpha-weighted value aggregation (f32x2, 2 dims/lane) ----
    const int j0 = 2 * lane;
    float2 wv[ED];
#pragma unroll
    for (int k = 0; k < ED; k++) wv[k] = *(const float2*)(valW1e + k * H + j0);

    float2 acc0 = make_float2(0.f, 0.f), acc1 = make_float2(0.f, 0.f);
    const int s0 = w * 128;
#pragma unroll 4
    for (int i = 0; i < 128; i += 4) {
        float4 wg4 = *(const float4*)(wexp[g] + s0 + i);
#pragma unroll
        for (int u = 0; u < 4; u++) {
            int s = s0 + i + u;
            float4 dA = eaA[g][s];
            float2 dB = eaB[g][s];
            float2 p = *(const float2*)(AvL + (size_t)s * H + j0);
            p = ffma2(dup2(dA.x), wv[0], p);
            p = ffma2(dup2(dA.y), wv[1], p);
            p = ffma2(dup2(dA.z), wv[2], p);
            p = ffma2(dup2(dA.w), wv[3], p);
            p = ffma2(dup2(dB.x), wv[4], p);
            p = ffma2(dup2(dB.y), wv[5], p);
            p.x = fmaxf(p.x, 0.f);
            p.y = fmaxf(p.y, 0.f);
            float wt = (u == 0) ? wg4.x : (u == 1) ? wg4.y : (u == 2) ? wg4.z : wg4.w;
            if (u & 1) acc1 = ffma2(dup2(wt), p, acc1);
            else       acc0 = ffma2(dup2(wt), p, acc0);
        }
    }
    acc0 = fadd2(acc0, acc1);
    *(float2*)(pacc[g] + w * H + j0) = acc0;
    __syncthreads();

    // ---- Combine 4 warp softmax partials ----
    if (tl < H) {
        float M = fmaxf(fmaxf(pm[g][0], pm[g][1]), fmaxf(pm[g][2], pm[g][3]));
        float sc0 = __expf(pm[g][0] - M), sc1 = __expf(pm[g][1] - M);
        float sc2 = __expf(pm[g][2] - M), sc3 = __expf(pm[g][3] - M);
        float stot = ps[g][0] * sc0 + ps[g][1] * sc1 + ps[g][2] * sc2 + ps[g][3] * sc3;
        float a = pacc[g][0 * H + tl] * sc0 + pacc[g][1 * H + tl] * sc1
                + pacc[g][2 * H + tl] * sc2 + pacc[g][3 * H + tl] * sc3;
        agg_sh[g][tl] = a / stot;
        h_sh[g][tl]   = g_h[d * H + tl];
    }
    __syncthreads();

    // ---- Node phase, 2-way k-split matvecs over 128 threads per group ----
    const int o = tl & 63, q = tl >> 6;

    // stage 1: tmp = val_b2 + agg @ val_w2
    {
        float p = 0.f;
        int k0 = q * 32;
#pragma unroll
        for (int kk = 0; kk < 32; kk++) p += agg_sh[g][k0 + kk] * valW2[(k0 + kk) * H + o];
        part2[g][q * H + o] = p;
    }
    __syncthreads();
    if (tl < H) tmp_sh[g][tl] = valB2[tl] + part2[g][tl] + part2[g][H + tl];
    __syncthreads();

    // stage 2: hid = relu(upd_b1 + [h,tmp] @ upd_w1)
    {
        const float* srcv = (q == 0) ? h_sh[g] : tmp_sh[g];
        int rbase = q * H;
        float p = 0.f;
#pragma unroll
        for (int kk = 0; kk < 64; kk++) p += srcv[kk] * updW1[(rbase + kk) * H + o];
        part2[g][q * H + o] = p;
    }
    __syncthreads();
    if (tl < H) hid_sh[g][tl] = fmaxf(updB1[tl] + part2[g][tl] + part2[g][H + tl], 0.f);
    __syncthreads();

    // stage 3: u = upd_b2 + hid @ upd_w2
    {
        float p = 0.f;
        int k0 = q * 32;
#pragma unroll
        for (int kk = 0; kk < 32; kk++) p += hid_sh[g][k0 + kk] * updW2[(k0 + kk) * H + o];
        part2[g][q * H + o] = p;
    }
    __syncthreads();

    // residual + LayerNorm (threads tl<64 = warps 0,1 of group; fused sum/sumsq)
    float r = 0.f, dr = 0.f;
    if (tl < H) {
        float u = updB2[tl] + part2[g][tl] + part2[g][H + tl];
        r = u + h_sh[g][tl];
        float s1 = warp_sum(r);
        float s2 = warp_sum(r * r);
        if (lane == 0) { red_sh[g][w] = s1; red_sh[g][w + 2] = s2; }
    }
    __syncthreads();
    if (tl < H) {
        float mu  = (red_sh[g][0] + red_sh[g][1]) * (1.0f / H);
        float ex2 = (red_sh[g][2] + red_sh[g][3]) * (1.0f / H);
        float var = ex2 - mu * mu;
        dr = r - mu;
        float hn = lng[tl] * dr * rsqrtf(var + LN_EPS) + lnb[tl];
        hn_sh[g][tl] = hn;
        if (!last) g_h[d * H + tl] = hn;
    }
    __syncthreads();

    if (!last) {
        if (tl < H)
            compute_tables(d, tl, wb, hn_sh[g], nattW1, nattB1, nvalW1, nvalB1);
    } else {
        if (tl < H) {
            float dh = decB1[tl];
#pragma unroll 8
            for (int k = 0; k < H; k++) dh += hn_sh[g][k] * decW1[k * H + tl];
            dh = fmaxf(dh, 0.f);
            float p = dh * decW2[tl];
            float psum = warp_sum(p);
            if (lane == 0) red_sh[g][w] = psum;
        }
        __syncthreads();
        if (tl == 0) out[d] = red_sh[g][0] + red_sh[g][1] + decB2[0];
    }
}

extern "C" void kernel_launch(void* const* d_in, const int* in_sizes, int n_in,
                              void* d_out, int out_size)
{
    const float* x      = (const float*)d_in[0];
    const float* ea     = (const float*)d_in[1];
    const float* enc_w1 = (const float*)d_in[2];
    const float* enc_b1 = (const float*)d_in[3];
    const float* enc_w2 = (const float*)d_in[4];
    const float* enc_b2 = (const float*)d_in[5];
    const float* att_w1 = (const float*)d_in[6];   // [4,134,64]
    const float* att_b1 = (const float*)d_in[7];   // [4,64]
    const float* att_w2 = (const float*)d_in[8];   // [4,64,1]
    // d_in[9] = att_b2 — cancels inside softmax, unused
    const float* val_w1 = (const float*)d_in[10];  // [4,70,64]
    const float* val_b1 = (const float*)d_in[11];  // [4,64]
    const float* val_w2 = (const float*)d_in[12];  // [4,64,64]
    const float* val_b2 = (const float*)d_in[13];  // [4,64]
    const float* upd_w1 = (const float*)d_in[14];  // [4,128,64]
    const float* upd_b1 = (const float*)d_in[15];  // [4,64]
    const float* upd_w2 = (const float*)d_in[16];  // [4,64,64]
    const float* upd_b2 = (const float*)d_in[17];  // [4,64]
    const float* ln_g   = (const float*)d_in[18];  // [4,64]
    const float* ln_b   = (const float*)d_in[19];  // [4,64]
    const float* dec_w1 = (const float*)d_in[20];
    const float* dec_b1 = (const float*)d_in[21];
    const float* dec_w2 = (const float*)d_in[22];
    const float* dec_b2 = (const float*)d_in[23];
    // d_in[24] = edge_index: src=e/512, dst=e%512 (structure exploited directly)

    float* out = (float*)d_out;

    ea_transpose_kernel<<<dim3(16, 16), 256>>>(ea);
    enc_kernel<<<NN, H>>>(x, enc_w1, enc_b1, enc_w2, enc_b2,
                          att_w1, att_b1, val_w1, val_b1);

    for (int l = 0; l < NL; l++) {
        int last = (l == NL - 1);
        int nl = (l + 1) % NL;      // dummy-but-valid pointers on last layer
        int rb = l & 1;             // enc wrote buffer 0; layer l reads l&1, writes (l&1)^1
        layer_kernel<<<NN / 2, 256>>>(att_w1 + (l * 134 + 128) * H,
                                  att_w2 + l * H,
                                  val_w1 + (l * 70 + 64) * H,
                                  val_w2 + l * H * H, val_b2 + l * H,
                                  upd_w1 + l * 2 * H * H, upd_b1 + l * H,
                                  upd_w2 + l * H * H, upd_b2 + l * H,
                                  ln_g + l * H, ln_b + l * H,
                                  att_w1 + nl * 134 * H, att_b1 + nl * H,
                                  val_w1 + nl * 70 * H, val_b1 + nl * H,
                                  dec_w1, dec_b1, dec_w2, dec_b2,
                                  out, rb, last);
    }
}